// round 12
// baseline (speedup 1.0000x reference)
#include <cuda_runtime.h>
#include <cstddef>

// GroupedESNCell, round 10: weights streamed L2->SMEM via cp.async.bulk
// (UBLKCP) into a 2-slot 80KB ring, removing the per-warp LDG MLP ceiling.
// Numerics identical class to R5-R7: int16 + int4 residual, per-row scales.
//
// Weight layout (built once by quantize_kernel): per CTA, 8 tiles of 80KB.
// Tile (cta, c): q16 region [128 rows x 256 cols x 2B = 64KB] then
//                wr  region [128 rows x 256 cols x 0.5B = 16KB].
// Row r, 8-col group j (cols 256c+8j..+7):
//   q16 at  tile + r*512 + j*16   (uint4: 4 pairs of biased u16)
//   wr  at  tile + 65536 + r*128 + j*4 (u32: 8 nibbles)

#define G 8
#define H 2048
#define T_STEPS 4096
#define NCTA 128
#define CTAS_PER_GROUP (NCTA / G)             // 16
#define ROWS_PER_CTA (H / CTAS_PER_GROUP)     // 128
#define THREADS 512
#define NWARPS (THREADS / 32)                 // 16
#define ROWS_PER_WARP (ROWS_PER_CTA / NWARPS) // 8
#define RADIUS_F 100.0f
#define LEAKY_F 1.0f
#define NROWS_TOTAL (G * H)                   // 16384
#define NGRP 256                              // 8-col groups per row
#define CHUNKS 8
#define TILE_Q16 65536
#define TILE_BYTES 81920
#define RING_BYTES (2 * TILE_BYTES)           // 160 KB dynamic smem

typedef unsigned long long u64;
#define NEGM2 0xCB008000CB008000ULL           // (-(2^23+32768)) x2 as f32x2

// ---- global scratch (allocation-free) ----
__device__ uint4 g_wt[(size_t)NCTA * CHUNKS * TILE_BYTES / 16];  // 84 MB tiles
__device__ float g_step[NROWS_TOTAL];
__device__ float g_pre[2][G * H];
__device__ float g_psq[2][NCTA];
__device__ unsigned int g_cnt[G * 32];
__device__ unsigned int g_epoch[G * 32];

// ============================================================================
// Prep A: per-row max|w| -> step = rowmax/32767 (one warp per row)
// ============================================================================
__global__ void rowscale_kernel(const float* __restrict__ W_hh)
{
    const int warp = threadIdx.x >> 5;
    const int lane = threadIdx.x & 31;
    const int row  = blockIdx.x * 8 + warp;
    const float* w = W_hh + (size_t)row * H;

    float m = 0.0f;
    #pragma unroll
    for (int k = 0; k < H / 32; ++k)
        m = fmaxf(m, fabsf(w[lane + 32 * k]));
    #pragma unroll
    for (int s = 16; s > 0; s >>= 1)
        m = fmaxf(m, __shfl_xor_sync(0xffffffffu, m, s));
    if (lane == 0)
        g_step[row] = fmaxf(m, 1e-30f) * (1.0f / 32767.0f);
}

// ============================================================================
// Prep B: quantize into tile layout. One thread per (row, 8-col group).
// ============================================================================
__global__ void quantize_kernel(const float* __restrict__ W_hh)
{
    const int gid = blockIdx.x * blockDim.x + threadIdx.x;
    if (gid >= NROWS_TOTAL * NGRP) return;
    const int row = gid >> 8;            // global row 0..16383
    const int grp = gid & 255;           // 8-col group 0..255
    const int c   = grp >> 5;            // chunk 0..7
    const int j   = grp & 31;            // group within chunk

    const int gg   = row >> 11;          // group id
    const int il   = row & 2047;         // row within group
    const int cta  = gg * CTAS_PER_GROUP + (il >> 7);
    const int lrow = il & 127;

    const float* wr = W_hh + (size_t)row * H + 256 * c + 8 * j;
    const float inv = 1.0f / g_step[row];

    float4 wa = *(const float4*)(wr);
    float4 wb = *(const float4*)(wr + 4);
    float v[8] = {wa.x, wa.y, wa.z, wa.w, wb.x, wb.y, wb.z, wb.w};

    unsigned int u16v[8];
    unsigned int nib = 0;
    #pragma unroll
    for (int k = 0; k < 8; ++k) {
        float s = v[k] * inv;
        int q = __float2int_rn(s);
        q = min(max(q, -32767), 32767);
        float r = s - (float)q;
        int q4 = __float2int_rn(r * 16.0f);
        q4 = min(max(q4, -8), 7);
        u16v[k] = (unsigned int)(q + 32768);
        nib |= (unsigned int)(q4 & 0xF) << (4 * k);
    }
    uint4 qs;
    qs.x = u16v[0] | (u16v[1] << 16);
    qs.y = u16v[2] | (u16v[3] << 16);
    qs.z = u16v[4] | (u16v[5] << 16);
    qs.w = u16v[6] | (u16v[7] << 16);

    char* tile = (char*)g_wt + (size_t)(cta * CHUNKS + c) * TILE_BYTES;
    *(uint4*)(tile + lrow * 512 + j * 16) = qs;
    *(unsigned int*)(tile + TILE_Q16 + lrow * 128 + j * 4) = nib;
}

// ============================================================================
// packed f32x2 / dequant helpers (as R7)
// ============================================================================
__device__ __forceinline__ u64 dq2(unsigned int p, u64 negm)
{
    u64 r;
    asm("{\n\t.reg .b32 lo, hi;\n\t"
        "prmt.b32 lo, %1, %2, 0x7610;\n\t"
        "prmt.b32 hi, %1, %2, 0x7632;\n\t"
        "mov.b64 %0, {lo, hi};\n\t"
        "add.rn.f32x2 %0, %0, %3;\n\t}"
        : "=l"(r) : "r"(p), "r"(0x4B000000u), "l"(negm));
    return r;
}
__device__ __forceinline__ u64 fma2(u64 a, u64 b, u64 c)
{
    u64 d;
    asm("fma.rn.f32x2 %0, %1, %2, %3;" : "=l"(d) : "l"(a), "l"(b), "l"(c));
    return d;
}
__device__ __forceinline__ float unpack_sum(u64 a)
{
    float lo, hi;
    asm("mov.b64 {%0, %1}, %2;" : "=f"(lo), "=f"(hi) : "l"(a));
    return lo + hi;
}
__device__ __forceinline__ unsigned int pack4(int a, int b, int c, int d)
{
    return (a & 0xFF) | ((b & 0xFF) << 8) | ((c & 0xFF) << 16) | ((d & 0xFF) << 24);
}
__device__ __forceinline__ void acc_res(int& dp, unsigned int x, uint2 hp)
{
    int e = (int)((x << 4) & 0xF0F0F0F0u);   // cols 0,2,4,6: 16*q4 as s8
    int o = (int)(x & 0xF0F0F0F0u);          // cols 1,3,5,7
    dp = __dp4a(e, (int)hp.x, dp);
    dp = __dp4a(o, (int)hp.y, dp);
}

// ---- mbarrier / bulk-copy primitives ----
__device__ __forceinline__ unsigned int smem_u32(const void* p)
{
    return (unsigned int)__cvta_generic_to_shared(p);
}
__device__ __forceinline__ void mbar_init(u64* m, unsigned int cnt)
{
    asm volatile("mbarrier.init.shared.b64 [%0], %1;"
                 :: "r"(smem_u32(m)), "r"(cnt) : "memory");
}
__device__ __forceinline__ void mbar_expect_tx(u64* m, unsigned int tx)
{
    asm volatile("mbarrier.arrive.expect_tx.shared.b64 _, [%0], %1;"
                 :: "r"(smem_u32(m)), "r"(tx) : "memory");
}
__device__ __forceinline__ void mbar_arrive(u64* m)
{
    asm volatile("mbarrier.arrive.shared.b64 _, [%0];"
                 :: "r"(smem_u32(m)) : "memory");
}
__device__ __forceinline__ void mbar_wait(u64* m, unsigned int parity)
{
    asm volatile(
        "{\n\t.reg .pred P1;\n\t"
        "WAIT_%=:\n\t"
        "mbarrier.try_wait.parity.acquire.cta.shared::cta.b64 P1, [%0], %1, 0x989680;\n\t"
        "@P1 bra.uni DONE_%=;\n\t"
        "bra.uni WAIT_%=;\n\t"
        "DONE_%=:\n\t}"
        :: "r"(smem_u32(m)), "r"(parity) : "memory");
}
__device__ __forceinline__ void bulk_g2s(void* dst_smem, const void* src,
                                         unsigned int bytes, u64* mbar)
{
    asm volatile(
        "cp.async.bulk.shared::cta.global.mbarrier::complete_tx::bytes "
        "[%0], [%1], %2, [%3];"
        :: "r"(smem_u32(dst_smem)), "l"(src), "r"(bytes),
           "r"(smem_u32(mbar)) : "memory");
}

// ============================================================================
// Persistent recurrence kernel
// ============================================================================
__global__ __launch_bounds__(THREADS, 1)
void esn_persistent_kernel(const float* __restrict__ x,
                           const float* __restrict__ W_ih,
                           float* __restrict__ out)
{
    extern __shared__ __align__(16) unsigned char ring[];   // 2 x 80KB

    __shared__ __align__(16) float h_sh[H];
    __shared__ __align__(8) uint2 hs8_sh[NGRP];
    __shared__ float x_sh[T_STEPS];
    __shared__ float wih_sh[ROWS_PER_CTA];
    __shared__ float step_sh[ROWS_PER_CTA];
    __shared__ float red_sh[NWARPS];
    __shared__ float coef_sh;
    __shared__ float hstep256_sh;
    __shared__ float invh_sh;
    __shared__ __align__(8) u64 mbar_full[2];
    __shared__ __align__(8) u64 mbar_empty[2];

    const int tid  = threadIdx.x;
    const int cta  = blockIdx.x;
    const int g    = cta / CTAS_PER_GROUP;
    const int sub  = cta % CTAS_PER_GROUP;
    const int rowbase = sub * ROWS_PER_CTA;
    const int warp = tid >> 5;
    const int lane = tid & 31;

    const float lr   = (LEAKY_F * (float)(G - g)) / (float)G;
    const float leak = 1.0f - lr;
    const u64 negm = NEGM2;

    const char* wtile = (const char*)g_wt + (size_t)cta * CHUNKS * TILE_BYTES;
    const ulonglong2* hs2 = (const ulonglong2*)h_sh;
    const float4* hs4 = (const float4*)h_sh;

    for (int i = tid; i < H; i += THREADS) h_sh[i] = 0.0f;
    for (int i = tid; i < NGRP; i += THREADS) hs8_sh[i] = make_uint2(0u, 0u);
    for (int i = tid; i < T_STEPS; i += THREADS) x_sh[i] = x[i];
    if (tid < ROWS_PER_CTA) {
        wih_sh[tid]  = W_ih[rowbase + tid];
        step_sh[tid] = g_step[g * H + rowbase + tid];
    }
    if (tid == 0) {
        hstep256_sh = 0.0f; invh_sh = 0.0f;
        mbar_init(&mbar_full[0], 1);
        mbar_init(&mbar_full[1], 1);
        mbar_init(&mbar_empty[0], NWARPS);
        mbar_init(&mbar_empty[1], NWARPS);
    }
    __syncthreads();

    // prologue: issue tiles 0 and 1 (slots are empty; skip empty-wait)
    if (tid == 0) {
        mbar_expect_tx(&mbar_full[0], TILE_BYTES);
        bulk_g2s(ring,              wtile,              TILE_BYTES, &mbar_full[0]);
        mbar_expect_tx(&mbar_full[1], TILE_BYTES);
        bulk_g2s(ring + TILE_BYTES, wtile + TILE_BYTES, TILE_BYTES, &mbar_full[1]);
    }

    unsigned int* const cntp = &g_cnt[g * 32];
    volatile unsigned int* const epop = (volatile unsigned int*)&g_epoch[g * 32];

    // pipeline cursors (per thread; producer uses pp*, consumers cph*)
    unsigned int cph0 = 0, cph1 = 0;     // consumer full-parity per slot
    unsigned int pp0 = 0, pp1 = 0;       // producer empty-parity per slot
    const int lastTile = T_STEPS * CHUNKS - 1;

    for (int t = 0; t < T_STEPS; ++t) {
        const int par = t & 1;
        const float xt = x_sh[t];
        const float hstep256 = hstep256_sh;

        // ======== Phase A: 8 tiles, 8 rows/warp, accumulate full dots =======
        u64 acc[ROWS_PER_WARP];
        int dpv[ROWS_PER_WARP];
        #pragma unroll
        for (int r = 0; r < ROWS_PER_WARP; ++r) { acc[r] = 0ULL; dpv[r] = 0; }

        #pragma unroll 1
        for (int c = 0; c < CHUNKS; ++c) {
            const int slot = c & 1;
            // consumer: wait tile ready
            mbar_wait(&mbar_full[slot], slot ? cph1 : cph0);
            if (slot) cph1 ^= 1u; else cph0 ^= 1u;

            const char* tb = (const char*)ring + slot * TILE_BYTES;
            const ulonglong2 ha = hs2[64 * c + 2 * lane];       // cols +0..3
            const ulonglong2 hb = hs2[64 * c + 2 * lane + 1];   // cols +4..7
            const uint2 hp = hs8_sh[32 * c + lane];
            const char* qb = tb + (warp * 8) * 512 + lane * 16;
            const char* rb = tb + TILE_Q16 + (warp * 8) * 128 + lane * 4;

            #pragma unroll
            for (int rr = 0; rr < ROWS_PER_WARP; ++rr) {
                uint4 q = *(const uint4*)(qb + rr * 512);
                unsigned int nb = *(const unsigned int*)(rb + rr * 128);
                acc[rr] = fma2(dq2(q.x, negm), ha.x, acc[rr]);
                acc[rr] = fma2(dq2(q.y, negm), ha.y, acc[rr]);
                acc[rr] = fma2(dq2(q.z, negm), hb.x, acc[rr]);
                acc[rr] = fma2(dq2(q.w, negm), hb.y, acc[rr]);
                acc_res(dpv[rr], nb, hp);
            }
            __syncwarp();
            if (lane == 0) mbar_arrive(&mbar_empty[slot]);

            // producer: refill this slot with tile (t*8 + c + 2)
            if (warp == 0) {
                if (lane == 0) {
                    const int n = t * CHUNKS + c + 2;
                    if (n <= lastTile) {
                        mbar_wait(&mbar_empty[slot], slot ? pp1 : pp0);
                        if (slot) pp1 ^= 1u; else pp0 ^= 1u;
                        mbar_expect_tx(&mbar_full[slot], TILE_BYTES);
                        bulk_g2s((void*)(ring + slot * TILE_BYTES),
                                 wtile + (size_t)((c + 2) & 7) * TILE_BYTES,
                                 TILE_BYTES, &mbar_full[slot]);
                    }
                }
                __syncwarp();
            }
        }

        // ======== epilogue: reduce, scale, store pre ========
        float vs[ROWS_PER_WARP];
        #pragma unroll
        for (int r = 0; r < ROWS_PER_WARP; ++r) {
            float v = fmaf(hstep256, (float)dpv[r], unpack_sum(acc[r]));
            #pragma unroll
            for (int s = 16; s > 0; s >>= 1)
                v += __shfl_xor_sync(0xffffffffu, v, s);
            vs[r] = v;
        }
        float warp_sq = 0.0f;
        if (lane == 0) {
            const int w8 = warp * 8;
            float p[8];
            #pragma unroll
            for (int r = 0; r < 8; ++r) {
                p[r] = fmaf(step_sh[w8 + r], vs[r], xt * wih_sh[w8 + r]);
                warp_sq += p[r] * p[r];
            }
            float4* dst = (float4*)&g_pre[par][g * H + rowbase + w8];
            __stcg(dst,     make_float4(p[0], p[1], p[2], p[3]));
            __stcg(dst + 1, make_float4(p[4], p[5], p[6], p[7]));
        }
        if (lane == 0) red_sh[warp] = warp_sq;
        __syncthreads();
        if (tid == 0) {
            float s = 0.0f;
            #pragma unroll
            for (int w = 0; w < NWARPS; ++w) s += red_sh[w];
            __stcg(&g_psq[par][cta], s);
        }

        // ======== per-group barrier ========
        __threadfence();
        if (tid == 0) {
            const unsigned int snap = *epop;
            const unsigned int old = atomicAdd(cntp, 1u);
            if (old == CTAS_PER_GROUP - 1u) {
                *cntp = 0u;
                __threadfence();
                atomicAdd((unsigned int*)epop, 1u);
            } else {
                while (*epop == snap) { }
            }
        }
        __syncthreads();
        __threadfence();

        // ======== Phase B: norm + state update + h8 repack ========
        if (tid == 0) {
            float s = 0.0f;
            #pragma unroll
            for (int c = 0; c < CTAS_PER_GROUP; ++c)
                s += __ldcg(&g_psq[par][g * CTAS_PER_GROUP + c]);
            coef_sh = lr * RADIUS_F * rsqrtf(s);
        }
        __syncthreads();
        const float cb = coef_sh;
        const float4* preg = (const float4*)&g_pre[par][g * H];
        float4* hmut = (float4*)h_sh;
        float m = 0.0f;
        {
            const int idx = tid;                 // 512 threads x float4 = H
            float4 p  = __ldcg(&preg[idx]);
            float4 hv = hmut[idx];
            hv.x = leak * hv.x + cb * p.x;
            hv.y = leak * hv.y + cb * p.y;
            hv.z = leak * hv.z + cb * p.z;
            hv.w = leak * hv.w + cb * p.w;
            hmut[idx] = hv;
            m = fmaxf(fmaxf(fabsf(hv.x), fabsf(hv.y)),
                      fmaxf(fabsf(hv.z), fabsf(hv.w)));
        }
        #pragma unroll
        for (int s = 16; s > 0; s >>= 1)
            m = fmaxf(m, __shfl_xor_sync(0xffffffffu, m, s));
        if (lane == 0) red_sh[warp] = m;
        __syncthreads();
        if (tid == 0) {
            float mm = 0.0f;
            #pragma unroll
            for (int w = 0; w < NWARPS; ++w) mm = fmaxf(mm, red_sh[w]);
            const float hstep = mm * (1.0f / 127.0f);
            hstep256_sh = hstep * (1.0f / 256.0f);
            invh_sh = (mm > 0.0f) ? 127.0f / mm : 0.0f;
        }
        __syncthreads();
        // pack h8: thread i handles cols 8i..8i+7
        if (tid < NGRP) {
            const float inv = invh_sh;
            float4 A = hs4[2 * tid];
            float4 B = hs4[2 * tid + 1];
            int q0 = __float2int_rn(A.x * inv);
            int q1 = __float2int_rn(A.y * inv);
            int q2 = __float2int_rn(A.z * inv);
            int q3 = __float2int_rn(A.w * inv);
            int q4 = __float2int_rn(B.x * inv);
            int q5 = __float2int_rn(B.y * inv);
            int q6 = __float2int_rn(B.z * inv);
            int q7 = __float2int_rn(B.w * inv);
            hs8_sh[tid] = make_uint2(pack4(q0, q2, q4, q6),
                                     pack4(q1, q3, q5, q7));
        }
        if (tid < ROWS_PER_CTA) {
            __stcs(&out[(size_t)t * (G * H) + (size_t)g * H + rowbase + tid],
                   h_sh[rowbase + tid]);
        }
        __syncthreads();
    }
}

extern "C" void kernel_launch(void* const* d_in, const int* in_sizes, int n_in,
                              void* d_out, int out_size)
{
    const float* x    = (const float*)d_in[0];   // [T, 1]
    const float* W_ih = (const float*)d_in[1];   // [H, 1]
    const float* W_hh = (const float*)d_in[2];   // [G, H, H]
    float* out = (float*)d_out;                  // [T, G*H]

    rowscale_kernel<<<NROWS_TOTAL / 8, 256>>>(W_hh);
    quantize_kernel<<<(NROWS_TOTAL * NGRP + 255) / 256, 256>>>(W_hh);

    cudaFuncSetAttribute(esn_persistent_kernel,
                         cudaFuncAttributeMaxDynamicSharedMemorySize,
                         RING_BYTES);
    esn_persistent_kernel<<<NCTA, THREADS, RING_BYTES>>>(x, W_ih, out);
}

// round 13
// speedup vs baseline: 1.0127x; 1.0127x over previous
#include <cuda_runtime.h>
#include <cstddef>

// GroupedESNCell, round 10: weights streamed L2->SMEM via cp.async.bulk
// (UBLKCP) into a 2-slot 80KB ring, removing the per-warp LDG MLP ceiling.
// Numerics identical class to R5-R7: int16 + int4 residual, per-row scales.
//
// Weight layout (built once by quantize_kernel): per CTA, 8 tiles of 80KB.
// Tile (cta, c): q16 region [128 rows x 256 cols x 2B = 64KB] then
//                wr  region [128 rows x 256 cols x 0.5B = 16KB].
// Row r, 8-col group j (cols 256c+8j..+7):
//   q16 at  tile + r*512 + j*16   (uint4: 4 pairs of biased u16)
//   wr  at  tile + 65536 + r*128 + j*4 (u32: 8 nibbles)

#define G 8
#define H 2048
#define T_STEPS 4096
#define NCTA 128
#define CTAS_PER_GROUP (NCTA / G)             // 16
#define ROWS_PER_CTA (H / CTAS_PER_GROUP)     // 128
#define THREADS 512
#define NWARPS (THREADS / 32)                 // 16
#define ROWS_PER_WARP (ROWS_PER_CTA / NWARPS) // 8
#define RADIUS_F 100.0f
#define LEAKY_F 1.0f
#define NROWS_TOTAL (G * H)                   // 16384
#define NGRP 256                              // 8-col groups per row
#define CHUNKS 8
#define TILE_Q16 65536
#define TILE_BYTES 81920
#define RING_BYTES (2 * TILE_BYTES)           // 160 KB dynamic smem

typedef unsigned long long u64;
#define NEGM2 0xCB008000CB008000ULL           // (-(2^23+32768)) x2 as f32x2

// ---- global scratch (allocation-free) ----
__device__ uint4 g_wt[(size_t)NCTA * CHUNKS * TILE_BYTES / 16];  // 84 MB tiles
__device__ float g_step[NROWS_TOTAL];
__device__ float g_pre[2][G * H];
__device__ float g_psq[2][NCTA];
__device__ unsigned int g_cnt[G * 32];
__device__ unsigned int g_epoch[G * 32];

// ============================================================================
// Prep A: per-row max|w| -> step = rowmax/32767 (one warp per row)
// ============================================================================
__global__ void rowscale_kernel(const float* __restrict__ W_hh)
{
    const int warp = threadIdx.x >> 5;
    const int lane = threadIdx.x & 31;
    const int row  = blockIdx.x * 8 + warp;
    const float* w = W_hh + (size_t)row * H;

    float m = 0.0f;
    #pragma unroll
    for (int k = 0; k < H / 32; ++k)
        m = fmaxf(m, fabsf(w[lane + 32 * k]));
    #pragma unroll
    for (int s = 16; s > 0; s >>= 1)
        m = fmaxf(m, __shfl_xor_sync(0xffffffffu, m, s));
    if (lane == 0)
        g_step[row] = fmaxf(m, 1e-30f) * (1.0f / 32767.0f);
}

// ============================================================================
// Prep B: quantize into tile layout. One thread per (row, 8-col group).
// ============================================================================
__global__ void quantize_kernel(const float* __restrict__ W_hh)
{
    const int gid = blockIdx.x * blockDim.x + threadIdx.x;
    if (gid >= NROWS_TOTAL * NGRP) return;
    const int row = gid >> 8;            // global row 0..16383
    const int grp = gid & 255;           // 8-col group 0..255
    const int c   = grp >> 5;            // chunk 0..7
    const int j   = grp & 31;            // group within chunk

    const int gg   = row >> 11;          // group id
    const int il   = row & 2047;         // row within group
    const int cta  = gg * CTAS_PER_GROUP + (il >> 7);
    const int lrow = il & 127;

    const float* wr = W_hh + (size_t)row * H + 256 * c + 8 * j;
    const float inv = 1.0f / g_step[row];

    float4 wa = *(const float4*)(wr);
    float4 wb = *(const float4*)(wr + 4);
    float v[8] = {wa.x, wa.y, wa.z, wa.w, wb.x, wb.y, wb.z, wb.w};

    unsigned int u16v[8];
    unsigned int nib = 0;
    #pragma unroll
    for (int k = 0; k < 8; ++k) {
        float s = v[k] * inv;
        int q = __float2int_rn(s);
        q = min(max(q, -32767), 32767);
        float r = s - (float)q;
        int q4 = __float2int_rn(r * 16.0f);
        q4 = min(max(q4, -8), 7);
        u16v[k] = (unsigned int)(q + 32768);
        nib |= (unsigned int)(q4 & 0xF) << (4 * k);
    }
    uint4 qs;
    qs.x = u16v[0] | (u16v[1] << 16);
    qs.y = u16v[2] | (u16v[3] << 16);
    qs.z = u16v[4] | (u16v[5] << 16);
    qs.w = u16v[6] | (u16v[7] << 16);

    char* tile = (char*)g_wt + (size_t)(cta * CHUNKS + c) * TILE_BYTES;
    *(uint4*)(tile + lrow * 512 + j * 16) = qs;
    *(unsigned int*)(tile + TILE_Q16 + lrow * 128 + j * 4) = nib;
}

// ============================================================================
// packed f32x2 / dequant helpers (as R7)
// ============================================================================
__device__ __forceinline__ u64 dq2(unsigned int p, u64 negm)
{
    u64 r;
    asm("{\n\t.reg .b32 lo, hi;\n\t"
        "prmt.b32 lo, %1, %2, 0x7610;\n\t"
        "prmt.b32 hi, %1, %2, 0x7632;\n\t"
        "mov.b64 %0, {lo, hi};\n\t"
        "add.rn.f32x2 %0, %0, %3;\n\t}"
        : "=l"(r) : "r"(p), "r"(0x4B000000u), "l"(negm));
    return r;
}
__device__ __forceinline__ u64 fma2(u64 a, u64 b, u64 c)
{
    u64 d;
    asm("fma.rn.f32x2 %0, %1, %2, %3;" : "=l"(d) : "l"(a), "l"(b), "l"(c));
    return d;
}
__device__ __forceinline__ float unpack_sum(u64 a)
{
    float lo, hi;
    asm("mov.b64 {%0, %1}, %2;" : "=f"(lo), "=f"(hi) : "l"(a));
    return lo + hi;
}
__device__ __forceinline__ unsigned int pack4(int a, int b, int c, int d)
{
    return (a & 0xFF) | ((b & 0xFF) << 8) | ((c & 0xFF) << 16) | ((d & 0xFF) << 24);
}
__device__ __forceinline__ void acc_res(int& dp, unsigned int x, uint2 hp)
{
    int e = (int)((x << 4) & 0xF0F0F0F0u);   // cols 0,2,4,6: 16*q4 as s8
    int o = (int)(x & 0xF0F0F0F0u);          // cols 1,3,5,7
    dp = __dp4a(e, (int)hp.x, dp);
    dp = __dp4a(o, (int)hp.y, dp);
}

// ---- mbarrier / bulk-copy primitives ----
__device__ __forceinline__ unsigned int smem_u32(const void* p)
{
    return (unsigned int)__cvta_generic_to_shared(p);
}
__device__ __forceinline__ void mbar_init(u64* m, unsigned int cnt)
{
    asm volatile("mbarrier.init.shared.b64 [%0], %1;"
                 :: "r"(smem_u32(m)), "r"(cnt) : "memory");
}
__device__ __forceinline__ void mbar_expect_tx(u64* m, unsigned int tx)
{
    asm volatile("mbarrier.arrive.expect_tx.shared.b64 _, [%0], %1;"
                 :: "r"(smem_u32(m)), "r"(tx) : "memory");
}
__device__ __forceinline__ void mbar_arrive(u64* m)
{
    asm volatile("mbarrier.arrive.shared.b64 _, [%0];"
                 :: "r"(smem_u32(m)) : "memory");
}
__device__ __forceinline__ void mbar_wait(u64* m, unsigned int parity)
{
    asm volatile(
        "{\n\t.reg .pred P1;\n\t"
        "WAIT_%=:\n\t"
        "mbarrier.try_wait.parity.acquire.cta.shared::cta.b64 P1, [%0], %1, 0x989680;\n\t"
        "@P1 bra.uni DONE_%=;\n\t"
        "bra.uni WAIT_%=;\n\t"
        "DONE_%=:\n\t}"
        :: "r"(smem_u32(m)), "r"(parity) : "memory");
}
__device__ __forceinline__ void bulk_g2s(void* dst_smem, const void* src,
                                         unsigned int bytes, u64* mbar)
{
    asm volatile(
        "cp.async.bulk.shared::cta.global.mbarrier::complete_tx::bytes "
        "[%0], [%1], %2, [%3];"
        :: "r"(smem_u32(dst_smem)), "l"(src), "r"(bytes),
           "r"(smem_u32(mbar)) : "memory");
}

// ============================================================================
// Persistent recurrence kernel
// ============================================================================
__global__ __launch_bounds__(THREADS, 1)
void esn_persistent_kernel(const float* __restrict__ x,
                           const float* __restrict__ W_ih,
                           float* __restrict__ out)
{
    extern __shared__ __align__(16) unsigned char ring[];   // 2 x 80KB

    __shared__ __align__(16) float h_sh[H];
    __shared__ __align__(8) uint2 hs8_sh[NGRP];
    __shared__ float x_sh[T_STEPS];
    __shared__ float wih_sh[ROWS_PER_CTA];
    __shared__ float step_sh[ROWS_PER_CTA];
    __shared__ float red_sh[NWARPS];
    __shared__ float coef_sh;
    __shared__ float hstep256_sh;
    __shared__ float invh_sh;
    __shared__ __align__(8) u64 mbar_full[2];
    __shared__ __align__(8) u64 mbar_empty[2];

    const int tid  = threadIdx.x;
    const int cta  = blockIdx.x;
    const int g    = cta / CTAS_PER_GROUP;
    const int sub  = cta % CTAS_PER_GROUP;
    const int rowbase = sub * ROWS_PER_CTA;
    const int warp = tid >> 5;
    const int lane = tid & 31;

    const float lr   = (LEAKY_F * (float)(G - g)) / (float)G;
    const float leak = 1.0f - lr;
    const u64 negm = NEGM2;

    const char* wtile = (const char*)g_wt + (size_t)cta * CHUNKS * TILE_BYTES;
    const ulonglong2* hs2 = (const ulonglong2*)h_sh;
    const float4* hs4 = (const float4*)h_sh;

    for (int i = tid; i < H; i += THREADS) h_sh[i] = 0.0f;
    for (int i = tid; i < NGRP; i += THREADS) hs8_sh[i] = make_uint2(0u, 0u);
    for (int i = tid; i < T_STEPS; i += THREADS) x_sh[i] = x[i];
    if (tid < ROWS_PER_CTA) {
        wih_sh[tid]  = W_ih[rowbase + tid];
        step_sh[tid] = g_step[g * H + rowbase + tid];
    }
    if (tid == 0) {
        hstep256_sh = 0.0f; invh_sh = 0.0f;
        mbar_init(&mbar_full[0], 1);
        mbar_init(&mbar_full[1], 1);
        mbar_init(&mbar_empty[0], NWARPS);
        mbar_init(&mbar_empty[1], NWARPS);
    }
    __syncthreads();

    // prologue: issue tiles 0 and 1 (slots are empty; skip empty-wait)
    if (tid == 0) {
        mbar_expect_tx(&mbar_full[0], TILE_BYTES);
        bulk_g2s(ring,              wtile,              TILE_BYTES, &mbar_full[0]);
        mbar_expect_tx(&mbar_full[1], TILE_BYTES);
        bulk_g2s(ring + TILE_BYTES, wtile + TILE_BYTES, TILE_BYTES, &mbar_full[1]);
    }

    unsigned int* const cntp = &g_cnt[g * 32];
    volatile unsigned int* const epop = (volatile unsigned int*)&g_epoch[g * 32];

    // pipeline cursors (per thread; producer uses pp*, consumers cph*)
    unsigned int cph0 = 0, cph1 = 0;     // consumer full-parity per slot
    unsigned int pp0 = 0, pp1 = 0;       // producer empty-parity per slot
    const int lastTile = T_STEPS * CHUNKS - 1;

    for (int t = 0; t < T_STEPS; ++t) {
        const int par = t & 1;
        const float xt = x_sh[t];
        const float hstep256 = hstep256_sh;

        // ======== Phase A: 8 tiles, 8 rows/warp, accumulate full dots =======
        u64 acc[ROWS_PER_WARP];
        int dpv[ROWS_PER_WARP];
        #pragma unroll
        for (int r = 0; r < ROWS_PER_WARP; ++r) { acc[r] = 0ULL; dpv[r] = 0; }

        #pragma unroll 1
        for (int c = 0; c < CHUNKS; ++c) {
            const int slot = c & 1;
            // consumer: wait tile ready
            mbar_wait(&mbar_full[slot], slot ? cph1 : cph0);
            if (slot) cph1 ^= 1u; else cph0 ^= 1u;

            const char* tb = (const char*)ring + slot * TILE_BYTES;
            const ulonglong2 ha = hs2[64 * c + 2 * lane];       // cols +0..3
            const ulonglong2 hb = hs2[64 * c + 2 * lane + 1];   // cols +4..7
            const uint2 hp = hs8_sh[32 * c + lane];
            const char* qb = tb + (warp * 8) * 512 + lane * 16;
            const char* rb = tb + TILE_Q16 + (warp * 8) * 128 + lane * 4;

            #pragma unroll
            for (int rr = 0; rr < ROWS_PER_WARP; ++rr) {
                uint4 q = *(const uint4*)(qb + rr * 512);
                unsigned int nb = *(const unsigned int*)(rb + rr * 128);
                acc[rr] = fma2(dq2(q.x, negm), ha.x, acc[rr]);
                acc[rr] = fma2(dq2(q.y, negm), ha.y, acc[rr]);
                acc[rr] = fma2(dq2(q.z, negm), hb.x, acc[rr]);
                acc[rr] = fma2(dq2(q.w, negm), hb.y, acc[rr]);
                acc_res(dpv[rr], nb, hp);
            }
            __syncwarp();
            if (lane == 0) mbar_arrive(&mbar_empty[slot]);

            // producer: refill this slot with tile (t*8 + c + 2)
            if (warp == 0) {
                if (lane == 0) {
                    const int n = t * CHUNKS + c + 2;
                    if (n <= lastTile) {
                        mbar_wait(&mbar_empty[slot], slot ? pp1 : pp0);
                        if (slot) pp1 ^= 1u; else pp0 ^= 1u;
                        mbar_expect_tx(&mbar_full[slot], TILE_BYTES);
                        bulk_g2s((void*)(ring + slot * TILE_BYTES),
                                 wtile + (size_t)((c + 2) & 7) * TILE_BYTES,
                                 TILE_BYTES, &mbar_full[slot]);
                    }
                }
                __syncwarp();
            }
        }

        // ======== epilogue: reduce, scale, store pre ========
        float vs[ROWS_PER_WARP];
        #pragma unroll
        for (int r = 0; r < ROWS_PER_WARP; ++r) {
            float v = fmaf(hstep256, (float)dpv[r], unpack_sum(acc[r]));
            #pragma unroll
            for (int s = 16; s > 0; s >>= 1)
                v += __shfl_xor_sync(0xffffffffu, v, s);
            vs[r] = v;
        }
        float warp_sq = 0.0f;
        if (lane == 0) {
            const int w8 = warp * 8;
            float p[8];
            #pragma unroll
            for (int r = 0; r < 8; ++r) {
                p[r] = fmaf(step_sh[w8 + r], vs[r], xt * wih_sh[w8 + r]);
                warp_sq += p[r] * p[r];
            }
            float4* dst = (float4*)&g_pre[par][g * H + rowbase + w8];
            __stcg(dst,     make_float4(p[0], p[1], p[2], p[3]));
            __stcg(dst + 1, make_float4(p[4], p[5], p[6], p[7]));
        }
        if (lane == 0) red_sh[warp] = warp_sq;
        __syncthreads();
        if (tid == 0) {
            float s = 0.0f;
            #pragma unroll
            for (int w = 0; w < NWARPS; ++w) s += red_sh[w];
            __stcg(&g_psq[par][cta], s);
        }

        // ======== per-group barrier ========
        __threadfence();
        if (tid == 0) {
            const unsigned int snap = *epop;
            const unsigned int old = atomicAdd(cntp, 1u);
            if (old == CTAS_PER_GROUP - 1u) {
                *cntp = 0u;
                __threadfence();
                atomicAdd((unsigned int*)epop, 1u);
            } else {
                while (*epop == snap) { }
            }
        }
        __syncthreads();
        __threadfence();

        // ======== Phase B: norm + state update + h8 repack ========
        if (tid == 0) {
            float s = 0.0f;
            #pragma unroll
            for (int c = 0; c < CTAS_PER_GROUP; ++c)
                s += __ldcg(&g_psq[par][g * CTAS_PER_GROUP + c]);
            coef_sh = lr * RADIUS_F * rsqrtf(s);
        }
        __syncthreads();
        const float cb = coef_sh;
        const float4* preg = (const float4*)&g_pre[par][g * H];
        float4* hmut = (float4*)h_sh;
        float m = 0.0f;
        {
            const int idx = tid;                 // 512 threads x float4 = H
            float4 p  = __ldcg(&preg[idx]);
            float4 hv = hmut[idx];
            hv.x = leak * hv.x + cb * p.x;
            hv.y = leak * hv.y + cb * p.y;
            hv.z = leak * hv.z + cb * p.z;
            hv.w = leak * hv.w + cb * p.w;
            hmut[idx] = hv;
            m = fmaxf(fmaxf(fabsf(hv.x), fabsf(hv.y)),
                      fmaxf(fabsf(hv.z), fabsf(hv.w)));
        }
        #pragma unroll
        for (int s = 16; s > 0; s >>= 1)
            m = fmaxf(m, __shfl_xor_sync(0xffffffffu, m, s));
        if (lane == 0) red_sh[warp] = m;
        __syncthreads();
        if (tid == 0) {
            float mm = 0.0f;
            #pragma unroll
            for (int w = 0; w < NWARPS; ++w) mm = fmaxf(mm, red_sh[w]);
            const float hstep = mm * (1.0f / 127.0f);
            hstep256_sh = hstep * (1.0f / 256.0f);
            invh_sh = (mm > 0.0f) ? 127.0f / mm : 0.0f;
        }
        __syncthreads();
        // pack h8: thread i handles cols 8i..8i+7
        if (tid < NGRP) {
            const float inv = invh_sh;
            float4 A = hs4[2 * tid];
            float4 B = hs4[2 * tid + 1];
            int q0 = __float2int_rn(A.x * inv);
            int q1 = __float2int_rn(A.y * inv);
            int q2 = __float2int_rn(A.z * inv);
            int q3 = __float2int_rn(A.w * inv);
            int q4 = __float2int_rn(B.x * inv);
            int q5 = __float2int_rn(B.y * inv);
            int q6 = __float2int_rn(B.z * inv);
            int q7 = __float2int_rn(B.w * inv);
            hs8_sh[tid] = make_uint2(pack4(q0, q2, q4, q6),
                                     pack4(q1, q3, q5, q7));
        }
        if (tid < ROWS_PER_CTA) {
            __stcs(&out[(size_t)t * (G * H) + (size_t)g * H + rowbase + tid],
                   h_sh[rowbase + tid]);
        }
        __syncthreads();
    }
}

extern "C" void kernel_launch(void* const* d_in, const int* in_sizes, int n_in,
                              void* d_out, int out_size)
{
    const float* x    = (const float*)d_in[0];   // [T, 1]
    const float* W_ih = (const float*)d_in[1];   // [H, 1]
    const float* W_hh = (const float*)d_in[2];   // [G, H, H]
    float* out = (float*)d_out;                  // [T, G*H]

    rowscale_kernel<<<NROWS_TOTAL / 8, 256>>>(W_hh);
    quantize_kernel<<<(NROWS_TOTAL * NGRP + 255) / 256, 256>>>(W_hh);

    cudaFuncSetAttribute(esn_persistent_kernel,
                         cudaFuncAttributeMaxDynamicSharedMemorySize,
                         RING_BYTES);
    esn_persistent_kernel<<<NCTA, THREADS, RING_BYTES>>>(x, W_ih, out);
}